// round 3
// baseline (speedup 1.0000x reference)
#include <cuda_runtime.h>
#include <cstdint>
#include <cfloat>

// ---------------------------------------------------------------------------
// SpanModel: cls, span_repr = spanMLP(spanmax,cls,width), top8(entity sims),
// star-GCN (2 layers) over gathered entities.
// ---------------------------------------------------------------------------

#define TPB 256
#define A_PAD 65
#define SMEM_FLOATS (256 * A_PAD + 64 * 128)
#define SMEM_BYTES (SMEM_FLOATS * 4)

enum { M_SPAN = 0, M_GCN1 = 1, M_GCN2 = 2, M_TOPK = 3 };

static const int NE = 50000;
static const int NROWS = 8192;       // Wmax*B*S
static const int ES = 7;             // entity splits
static const int ECHUNK = 7168;      // 56*128 — keeps every segment 128-aligned

// ------------------------- scratch (device globals) -----------------------
__device__ float g_ETt[256L * 50000];       // entity_table transposed [k][e]
__device__ float g_spanmax[8L * 1024 * 256];// [w][b][s][h] row n = w*1024+b*256+s
__device__ float g_rowbias[32 * 256];       // per (w,b) bias row
__device__ float g_pv[(long)ES * 8192 * 8]; // partial top-8 values
__device__ int   g_pi[(long)ES * 8192 * 8]; // partial top-8 indices
__device__ int   g_topk[8192L * 8];         // final sorted top-8 indices
__device__ float g_mixed[65536L * 256];     // star-mixed features
__device__ float g_hbuf[65536L * 256];      // relu hidden

// ------------------------- helpers ----------------------------------------
__device__ __forceinline__ bool better(float v1, int i1, float v2, int i2) {
    return (v1 > v2) || (v1 == v2 && i1 < i2);
}

__device__ __forceinline__ void insert8(float tv[8], int ti[8], float v, int e) {
    if (better(v, e, tv[7], ti[7])) {
        tv[7] = v; ti[7] = e;
#pragma unroll
        for (int j = 7; j > 0; --j) {
            if (better(tv[j], ti[j], tv[j - 1], ti[j - 1])) {
                float fv = tv[j]; tv[j] = tv[j - 1]; tv[j - 1] = fv;
                int ii = ti[j]; ti[j] = ti[j - 1]; ti[j - 1] = ii;
            }
        }
    }
}

// ------------------------- small kernels -----------------------------------

// entity_table [NE][256] -> g_ETt [256][NE]
__global__ void k_transpose(const float* __restrict__ ET) {
    __shared__ float t[32][33];
    int e0 = blockIdx.x * 32, k0 = blockIdx.y * 32;
    int tx = threadIdx.x, ty = threadIdx.y;
#pragma unroll
    for (int i = 0; i < 4; i++) {
        int e = e0 + ty + 8 * i;
        if (e < NE) t[ty + 8 * i][tx] = ET[(size_t)e * 256 + k0 + tx];
    }
    __syncthreads();
#pragma unroll
    for (int i = 0; i < 4; i++) {
        int k = k0 + ty + 8 * i;
        int e = e0 + tx;
        if (e < NE) g_ETt[(size_t)k * NE + e] = t[tx][ty + 8 * i];
    }
}

// cls out + running span max over widths 1..8
__global__ void k_spanprep(const float* __restrict__ emb, float* __restrict__ out_cls) {
    int g = blockIdx.x * TPB + threadIdx.x;   // b*65536 + s*256 + h
    int h = g & 255, s = (g >> 8) & 255, b = g >> 16;
    float v0 = emb[g];
    float cur = v0;
    g_spanmax[g] = cur;
#pragma unroll
    for (int w = 1; w < 8; ++w) {
        if (s + w < 256) cur = fmaxf(cur, emb[((size_t)b * 256 + s + w) * 256 + h]);
        g_spanmax[(size_t)w * 262144 + g] = cur;
    }
    if (s == 0) out_cls[b * 256 + h] = v0;
}

// rowbias[w*4+b][h] = span_b[h] + (w+1)*W[512][h] + sum_j cls[b][j]*W[256+j][h]
__global__ void k_rowbias(const float* __restrict__ emb, const float* __restrict__ spanW,
                          const float* __restrict__ spanb) {
    int bw = blockIdx.x;
    int w = bw >> 2, b = bw & 3;
    int h = threadIdx.x;
    __shared__ float cls_s[256];
    cls_s[h] = emb[(size_t)b * 65536 + h];
    __syncthreads();
    float acc = spanb[h] + (float)(w + 1) * spanW[512 * 256 + h];
    for (int j = 0; j < 256; ++j)
        acc = fmaf(cls_s[j], spanW[(256 + j) * 256 + h], acc);
    g_rowbias[bw * 256 + h] = acc;
}

// ------------------------- GEMM core ---------------------------------------

// load A tile [row0..row0+63][0..255] transposed into a_sm[k][row] (pad 65)
__device__ __forceinline__ void fill_a(float* a_sm, const float* __restrict__ A,
                                       int row0, int tid) {
#pragma unroll
    for (int it = 0; it < 16; ++it) {
        int f = tid + 256 * it;   // 0..4095
        int r = f >> 6;
        int q = f & 63;
        float4 v = *(const float4*)&A[((size_t)(row0 + r)) * 256 + 4 * q];
        a_sm[(4 * q + 0) * A_PAD + r] = v.x;
        a_sm[(4 * q + 1) * A_PAD + r] = v.y;
        a_sm[(4 * q + 2) * A_PAD + r] = v.z;
        a_sm[(4 * q + 3) * A_PAD + r] = v.w;
    }
}

// load B chunk: rows k = kc*64..+63, cols colBase..+127 from row-major [k][ldb]
// colBase MUST be a multiple of 4 (float4 alignment).
template <bool GUARD>
__device__ __forceinline__ void fill_b(float* b_sm, const float* __restrict__ Bg,
                                       int ldb, int colBase, int kc, int nCols, int tid) {
#pragma unroll
    for (int it = 0; it < 8; ++it) {
        int f = tid + 256 * it;   // 0..2047
        int kk = f >> 5;          // 0..63
        int e4 = f & 31;          // 0..31
        int gc = colBase + 4 * e4;
        float4 v = make_float4(0.f, 0.f, 0.f, 0.f);
        if (!GUARD || gc < nCols)
            v = *(const float4*)&Bg[((size_t)(kc * 64 + kk)) * ldb + gc];
        int cx = ((kk >> 3) & 7) << 2;
        *(float4*)&b_sm[kk * 128 + ((4 * e4) ^ cx)] = v;
    }
}

__device__ __forceinline__ void compute_chunk(const float* __restrict__ a_sm,
                                              const float* __restrict__ b_sm,
                                              float acc[4][8], int kc, int rb, int tc) {
    const int cA = tc * 4;
    const int cB = 64 + tc * 4;
#pragma unroll 8
    for (int kk = 0; kk < 64; ++kk) {
        int kg = kc * 64 + kk;
        float a0 = a_sm[kg * A_PAD + rb + 0];
        float a1 = a_sm[kg * A_PAD + rb + 1];
        float a2 = a_sm[kg * A_PAD + rb + 2];
        float a3 = a_sm[kg * A_PAD + rb + 3];
        int cx = ((kk >> 3) & 7) << 2;
        const float4 b0 = *(const float4*)&b_sm[kk * 128 + (cA ^ cx)];
        const float4 b1 = *(const float4*)&b_sm[kk * 128 + (cB ^ cx)];
        float bj[8] = {b0.x, b0.y, b0.z, b0.w, b1.x, b1.y, b1.z, b1.w};
        float ai[4] = {a0, a1, a2, a3};
#pragma unroll
        for (int i = 0; i < 4; ++i)
#pragma unroll
            for (int j = 0; j < 8; ++j)
                acc[i][j] = fmaf(ai[i], bj[j], acc[i][j]);
    }
}

// MODE: M_SPAN / M_GCN1 / M_GCN2 write C; M_TOPK runs fused top-8.
template <int MODE>
__global__ void __launch_bounds__(256, 2)
gemm_k(const float* __restrict__ A, const float* __restrict__ Bg, int ldb,
       const float* __restrict__ bias, float* __restrict__ C,
       int nMtiles, int eChunk) {
    extern __shared__ float sm[];
    float* a_sm = sm;
    float* b_sm = sm + 256 * A_PAD;
    int tid = threadIdx.x;

    int mt, nt = 0, eb = 0;
    if (MODE == M_TOPK) { mt = blockIdx.x % nMtiles; eb = blockIdx.x / nMtiles; }
    else { mt = blockIdx.x >> 1; nt = blockIdx.x & 1; }

    int row0 = mt * 64;
    fill_a(a_sm, A, row0, tid);
    __syncthreads();

    int trow = tid >> 4, tc = tid & 15;
    int rb = trow * 4;

    if (MODE == M_TOPK) {
        float tv[8]; int ti[8];
#pragma unroll
        for (int j = 0; j < 8; ++j) { tv[j] = -FLT_MAX; ti[j] = 0x7FFFFFFF; }

        int bStart = eb * eChunk;
        int bEnd = bStart + eChunk; if (bEnd > NE) bEnd = NE;

        for (int te0 = bStart; te0 < bEnd; te0 += 128) {
            float acc[4][8];
#pragma unroll
            for (int i = 0; i < 4; ++i)
#pragma unroll
                for (int j = 0; j < 8; ++j) acc[i][j] = 0.f;

#pragma unroll 1
            for (int kc = 0; kc < 4; ++kc) {
                __syncthreads();
                fill_b<true>(b_sm, Bg, ldb, te0, kc, NE, tid);
                __syncthreads();
                compute_chunk(a_sm, b_sm, acc, kc, rb, tc);
            }
            __syncthreads();
            // dump sims into b_sm [64 rows][128 cols] (unswizzled)
#pragma unroll
            for (int i = 0; i < 4; ++i) {
                *(float4*)&b_sm[(rb + i) * 128 + tc * 4] =
                    make_float4(acc[i][0], acc[i][1], acc[i][2], acc[i][3]);
                *(float4*)&b_sm[(rb + i) * 128 + 64 + tc * 4] =
                    make_float4(acc[i][4], acc[i][5], acc[i][6], acc[i][7]);
            }
            __syncthreads();
            // scan: 4 threads per row, 32 cols each, rotated for bank spread
            int rowS = tid >> 2, qS = tid & 3;
#pragma unroll 1
            for (int j = 0; j < 32; ++j) {
                int col = qS * 32 + ((j + tid) & 31);
                int e = te0 + col;
                if (e < bEnd) {
                    float v = b_sm[rowS * 128 + col];
                    insert8(tv, ti, v, e);
                }
            }
        }

        // block-level per-row merge of the 4 quarter streams
        __syncthreads();
        float* cv = b_sm;                 // [64][32]
        int* ci = (int*)(b_sm + 2048);    // [64][32]
        {
            int rowS = tid >> 2, qS = tid & 3;
#pragma unroll
            for (int j = 0; j < 8; ++j) {
                cv[rowS * 32 + qS * 8 + j] = tv[j];
                ci[rowS * 32 + qS * 8 + j] = ti[j];
            }
        }
        __syncthreads();
        if (tid < 64) {
            float mv[8]; int mi[8];
#pragma unroll
            for (int j = 0; j < 8; ++j) { mv[j] = -FLT_MAX; mi[j] = 0x7FFFFFFF; }
            for (int q = 0; q < 32; ++q)
                insert8(mv, mi, cv[tid * 32 + q], ci[tid * 32 + q]);
            size_t base = ((size_t)eb * NROWS + row0 + tid) * 8;
#pragma unroll
            for (int j = 0; j < 8; ++j) { g_pv[base + j] = mv[j]; g_pi[base + j] = mi[j]; }
        }
    } else {
        float acc[4][8];
#pragma unroll
        for (int i = 0; i < 4; ++i)
#pragma unroll
            for (int j = 0; j < 8; ++j) acc[i][j] = 0.f;

#pragma unroll 1
        for (int kc = 0; kc < 4; ++kc) {
            if (kc) __syncthreads();
            fill_b<false>(b_sm, Bg, ldb, nt * 128, kc, 0, tid);
            __syncthreads();
            compute_chunk(a_sm, b_sm, acc, kc, rb, tc);
        }

        int c0 = nt * 128 + tc * 4;
        int c1 = c0 + 64;
        if (MODE == M_GCN1 || MODE == M_GCN2) {
            float bv0[4], bv1[4];
#pragma unroll
            for (int j = 0; j < 4; ++j) { bv0[j] = bias[c0 + j]; bv1[j] = bias[c1 + j]; }
#pragma unroll
            for (int i = 0; i < 4; ++i) {
                size_t ro = (size_t)(row0 + rb + i) * 256;
                float o[8];
#pragma unroll
                for (int j = 0; j < 4; ++j) {
                    o[j] = acc[i][j] + bv0[j];
                    o[4 + j] = acc[i][4 + j] + bv1[j];
                }
                if (MODE == M_GCN1) {
#pragma unroll
                    for (int j = 0; j < 8; ++j) o[j] = fmaxf(o[j], 0.f);
                }
                *(float4*)&C[ro + c0] = make_float4(o[0], o[1], o[2], o[3]);
                *(float4*)&C[ro + c1] = make_float4(o[4], o[5], o[6], o[7]);
            }
        } else { // M_SPAN: per-(w,b) row bias
#pragma unroll
            for (int i = 0; i < 4; ++i) {
                int row = row0 + rb + i;
                const float* rbp = bias + ((row >> 8) * 256);
                size_t ro = (size_t)row * 256;
                float o[8];
#pragma unroll
                for (int j = 0; j < 4; ++j) {
                    o[j] = acc[i][j] + rbp[c0 + j];
                    o[4 + j] = acc[i][4 + j] + rbp[c1 + j];
                }
                *(float4*)&C[ro + c0] = make_float4(o[0], o[1], o[2], o[3]);
                *(float4*)&C[ro + c1] = make_float4(o[4], o[5], o[6], o[7]);
            }
        }
    }
}

// final ES-way merge -> sorted top-8 indices per row
__global__ void k_merge() {
    int r = blockIdx.x * TPB + threadIdx.x;
    float tv[8]; int ti[8];
#pragma unroll
    for (int j = 0; j < 8; ++j) { tv[j] = -FLT_MAX; ti[j] = 0x7FFFFFFF; }
    for (int p = 0; p < ES; ++p) {
        size_t base = ((size_t)p * NROWS + r) * 8;
#pragma unroll
        for (int j = 0; j < 8; ++j)
            insert8(tv, ti, g_pv[base + j], g_pi[base + j]);
    }
#pragma unroll
    for (int j = 0; j < 8; ++j) g_topk[(size_t)r * 8 + j] = ti[j];
}

// gather + star mix (layer 1 input)
__global__ void k_mix1(const float* __restrict__ ET) {
    int n = blockIdx.x, h = threadIdx.x;
    __shared__ int id[8];
    if (h < 8) id[h] = g_topk[n * 8 + h];
    __syncthreads();
    float x0 = ET[(size_t)id[0] * 256 + h];
    float s = 0.f;
    float* outb = g_mixed + (size_t)n * 8 * 256 + h;
#pragma unroll
    for (int j = 1; j < 8; ++j) {
        float xj = ET[(size_t)id[j] * 256 + h];
        s += xj;
        outb[j * 256] = 0.25f * x0 + 0.5f * xj;
    }
    outb[0] = 0.125f * x0 + 0.25f * s;
}

// star mix of hidden (layer 2 input)
__global__ void k_mix2() {
    int n = blockIdx.x, h = threadIdx.x;
    const float* inb = g_hbuf + (size_t)n * 8 * 256 + h;
    float* outb = g_mixed + (size_t)n * 8 * 256 + h;
    float x0 = inb[0];
    float s = 0.f;
#pragma unroll
    for (int j = 1; j < 8; ++j) {
        float xj = inb[j * 256];
        s += xj;
        outb[j * 256] = 0.25f * x0 + 0.5f * xj;
    }
    outb[0] = 0.125f * x0 + 0.25f * s;
}

// ------------------------- host --------------------------------------------
extern "C" void kernel_launch(void* const* d_in, const int* in_sizes, int n_in,
                              void* d_out, int out_size) {
    const float* emb = (const float*)d_in[0];
    const float* ET = (const float*)d_in[1];
    const float* spanW = (const float*)d_in[2];
    const float* spanb = (const float*)d_in[3];
    const float* W1 = (const float*)d_in[4];
    const float* b1 = (const float*)d_in[5];
    const float* W2 = (const float*)d_in[6];
    const float* b2 = (const float*)d_in[7];

    float* out = (float*)d_out;
    float* out_cls = out;                       // 4*256
    float* out_spanrepr = out + 1024;           // 8192*256
    float* out_sub = out + 1024 + 8192 * 256;   // 65536*256

    float *ETt, *spanmax, *rowbias, *mixed, *hbuf;
    cudaGetSymbolAddress((void**)&ETt, g_ETt);
    cudaGetSymbolAddress((void**)&spanmax, g_spanmax);
    cudaGetSymbolAddress((void**)&rowbias, g_rowbias);
    cudaGetSymbolAddress((void**)&mixed, g_mixed);
    cudaGetSymbolAddress((void**)&hbuf, g_hbuf);

    cudaFuncSetAttribute(gemm_k<M_SPAN>, cudaFuncAttributeMaxDynamicSharedMemorySize, SMEM_BYTES);
    cudaFuncSetAttribute(gemm_k<M_GCN1>, cudaFuncAttributeMaxDynamicSharedMemorySize, SMEM_BYTES);
    cudaFuncSetAttribute(gemm_k<M_GCN2>, cudaFuncAttributeMaxDynamicSharedMemorySize, SMEM_BYTES);
    cudaFuncSetAttribute(gemm_k<M_TOPK>, cudaFuncAttributeMaxDynamicSharedMemorySize, SMEM_BYTES);

    // 1) transpose entity table
    k_transpose<<<dim3((NE + 31) / 32, 8), dim3(32, 8)>>>(ET);
    // 2) cls + span max
    k_spanprep<<<1024, TPB>>>(emb, out_cls);
    // 3) per-(w,b) bias rows
    k_rowbias<<<32, TPB>>>(emb, spanW, spanb);
    // 4) span_repr = spanmax @ W[0:256] + rowbias
    gemm_k<M_SPAN><<<256, TPB, SMEM_BYTES>>>(spanmax, spanW, 256, rowbias,
                                             out_spanrepr, 128, 0);
    // 5) fused sims GEMM + per-segment top-8
    gemm_k<M_TOPK><<<128 * ES, TPB, SMEM_BYTES>>>(out_spanrepr, ETt, NE, nullptr,
                                                  nullptr, 128, ECHUNK);
    // 6) merge segments -> sorted top-8 indices
    k_merge<<<NROWS / TPB, TPB>>>();
    // 7) gather + star mix
    k_mix1<<<NROWS, TPB>>>(ET);
    // 8) hidden = relu(mixed @ W1 + b1)
    gemm_k<M_GCN1><<<2048, TPB, SMEM_BYTES>>>(mixed, W1, 256, b1, hbuf, 1024, 0);
    // 9) star mix of hidden
    k_mix2<<<NROWS, TPB>>>();
    // 10) subgraph_out = mixed2 @ W2 + b2
    gemm_k<M_GCN2><<<2048, TPB, SMEM_BYTES>>>(mixed, W2, 256, b2, out_sub, 1024, 0);

    (void)in_sizes; (void)n_in; (void)out_size;
}

// round 5
// speedup vs baseline: 3.0164x; 3.0164x over previous
#include <cuda_runtime.h>
#include <cuda_bf16.h>
#include <cstdint>
#include <cfloat>

// ---------------------------------------------------------------------------
// SpanModel: cls, span_repr = spanMLP(spanmax,cls,width), top8(entity sims),
// star-GCN (2 layers). sims via mma.sync bf16 filter + exact fp32 refine.
// ---------------------------------------------------------------------------

#define TPB 256
#define A_PAD 65
#define SMEM_FLOATS (256 * A_PAD + 64 * 128)
#define SMEM_BYTES (SMEM_FLOATS * 4)

enum { M_SPAN = 0, M_GCN1 = 1, M_GCN2 = 2 };

static const int NE = 50000;
static const int NROWS = 8192;       // Wmax*B*S
static const int ESEG = 25088;       // 196*128 entity split point

// ------------------------- scratch (device globals) -----------------------
__device__ __nv_bfloat16 g_ETbf[50000L * 256]; // bf16 entity table
__device__ float g_spanmax[8L * 1024 * 256];   // [w][b][s][h]
__device__ float g_rowbias[32 * 256];          // per (w,b) bias row
__device__ int   g_cand[2L * 8192 * 16];       // candidate indices per eseg
__device__ int   g_topk[8192L * 8];            // final sorted top-8 indices
__device__ float g_mixed[65536L * 256];        // star-mixed features
__device__ float g_hbuf[65536L * 256];         // relu hidden

// ------------------------- PTX helpers -------------------------------------
__device__ __forceinline__ uint32_t smem_u32(const void* p) {
    uint32_t a;
    asm("{ .reg .u64 t; cvta.to.shared.u64 t, %1; cvt.u32.u64 %0, t; }"
        : "=r"(a) : "l"(p));
    return a;
}

#define STS32(addr, v) \
    asm volatile("st.shared.b32 [%0], %1;" :: "r"(addr), "r"(v) : "memory")
#define STS128(addr, a, b, c, d) \
    asm volatile("st.shared.v4.b32 [%0], {%1,%2,%3,%4};" \
                 :: "r"(addr), "r"(a), "r"(b), "r"(c), "r"(d) : "memory")
#define CP16(dst, src) \
    asm volatile("cp.async.cg.shared.global [%0], [%1], 16;" \
                 :: "r"(dst), "l"(src) : "memory")
#define CP_COMMIT() asm volatile("cp.async.commit_group;" ::: "memory")
#define CP_WAIT1() asm volatile("cp.async.wait_group 1;" ::: "memory")

#define LDMX4(r0, r1, r2, r3, addr) \
    asm volatile("ldmatrix.sync.aligned.m8n8.x4.shared.b16 {%0,%1,%2,%3}, [%4];" \
                 : "=r"(r0), "=r"(r1), "=r"(r2), "=r"(r3) : "r"(addr))

#define MMA16816(c, a0, a1, a2, a3, b0, b1) \
    asm volatile("mma.sync.aligned.m16n8k16.row.col.f32.bf16.bf16.f32 " \
                 "{%0,%1,%2,%3}, {%4,%5,%6,%7}, {%8,%9}, {%0,%1,%2,%3};" \
                 : "+f"((c)[0]), "+f"((c)[1]), "+f"((c)[2]), "+f"((c)[3]) \
                 : "r"(a0), "r"(a1), "r"(a2), "r"(a3), "r"(b0), "r"(b1))

// blocked SW128 layout for a 128-row x 512-byte bf16 tile (64 atoms x 1KB)
__device__ __forceinline__ uint32_t tileoff(int r, int cb) {
    int b = ((r >> 3) + (cb >> 7) * 16) * 1024 + (r & 7) * 128 + (cb & 127);
    return (uint32_t)(b ^ ((b >> 3) & 0x70));
}

// ------------------------- top-k helpers -----------------------------------
__device__ __forceinline__ bool better(float v1, int i1, float v2, int i2) {
    return (v1 > v2) || (v1 == v2 && i1 < i2);
}

__device__ __forceinline__ void insert8(float tv[8], int ti[8], float v, int e) {
    if (better(v, e, tv[7], ti[7])) {
        tv[7] = v; ti[7] = e;
#pragma unroll
        for (int j = 7; j > 0; --j) {
            if (better(tv[j], ti[j], tv[j - 1], ti[j - 1])) {
                float fv = tv[j]; tv[j] = tv[j - 1]; tv[j - 1] = fv;
                int ii = ti[j]; ti[j] = ti[j - 1]; ti[j - 1] = ii;
            }
        }
    }
}

__device__ __noinline__ void insert16_slow(float* tv, int* ti, float v, int e) {
    int q = 15;
    while (q > 0 && better(v, e, tv[q - 1], ti[q - 1])) {
        tv[q] = tv[q - 1]; ti[q] = ti[q - 1]; --q;
    }
    tv[q] = v; ti[q] = e;
}

// ------------------------- small kernels -----------------------------------

__global__ void k_etbf(const float* __restrict__ ET) {
    int g = blockIdx.x * 256 + threadIdx.x;      // one per 4 elements
    float4 v = *(const float4*)&ET[(size_t)g * 4];
    __nv_bfloat162 lo = {__float2bfloat16(v.x), __float2bfloat16(v.y)};
    __nv_bfloat162 hi = {__float2bfloat16(v.z), __float2bfloat16(v.w)};
    uint2 o = {*(uint32_t*)&lo, *(uint32_t*)&hi};
    *(uint2*)&g_ETbf[(size_t)g * 4] = o;
}

// cls out + running span max over widths 1..8
__global__ void k_spanprep(const float* __restrict__ emb, float* __restrict__ out_cls) {
    int g = blockIdx.x * TPB + threadIdx.x;   // b*65536 + s*256 + h
    int h = g & 255, s = (g >> 8) & 255, b = g >> 16;
    float v0 = emb[g];
    float cur = v0;
    g_spanmax[g] = cur;
#pragma unroll
    for (int w = 1; w < 8; ++w) {
        if (s + w < 256) cur = fmaxf(cur, emb[((size_t)b * 256 + s + w) * 256 + h]);
        g_spanmax[(size_t)w * 262144 + g] = cur;
    }
    if (s == 0) out_cls[b * 256 + h] = v0;
}

// rowbias[w*4+b][h] = span_b[h] + (w+1)*W[512][h] + sum_j cls[b][j]*W[256+j][h]
__global__ void k_rowbias(const float* __restrict__ emb, const float* __restrict__ spanW,
                          const float* __restrict__ spanb) {
    int bw = blockIdx.x;
    int w = bw >> 2, b = bw & 3;
    int h = threadIdx.x;
    __shared__ float cls_s[256];
    cls_s[h] = emb[(size_t)b * 65536 + h];
    __syncthreads();
    float acc = spanb[h] + (float)(w + 1) * spanW[512 * 256 + h];
    for (int j = 0; j < 256; ++j)
        acc = fmaf(cls_s[j], spanW[(256 + j) * 256 + h], acc);
    g_rowbias[bw * 256 + h] = acc;
}

// ------------------------- FFMA GEMM (span/GCN) ----------------------------

__device__ __forceinline__ void fill_a(float* a_sm, const float* __restrict__ A,
                                       int row0, int tid) {
#pragma unroll
    for (int it = 0; it < 16; ++it) {
        int f = tid + 256 * it;
        int r = f >> 6;
        int q = f & 63;
        float4 v = *(const float4*)&A[((size_t)(row0 + r)) * 256 + 4 * q];
        a_sm[(4 * q + 0) * A_PAD + r] = v.x;
        a_sm[(4 * q + 1) * A_PAD + r] = v.y;
        a_sm[(4 * q + 2) * A_PAD + r] = v.z;
        a_sm[(4 * q + 3) * A_PAD + r] = v.w;
    }
}

__device__ __forceinline__ void fill_b(float* b_sm, const float* __restrict__ Bg,
                                       int ldb, int colBase, int kc, int tid) {
#pragma unroll
    for (int it = 0; it < 8; ++it) {
        int f = tid + 256 * it;
        int kk = f >> 5;
        int e4 = f & 31;
        int gc = colBase + 4 * e4;
        float4 v = *(const float4*)&Bg[((size_t)(kc * 64 + kk)) * ldb + gc];
        int cx = ((kk >> 3) & 7) << 2;
        *(float4*)&b_sm[kk * 128 + ((4 * e4) ^ cx)] = v;
    }
}

__device__ __forceinline__ void compute_chunk(const float* __restrict__ a_sm,
                                              const float* __restrict__ b_sm,
                                              float acc[4][8], int kc, int rb, int tc) {
    const int cA = tc * 4;
    const int cB = 64 + tc * 4;
#pragma unroll 8
    for (int kk = 0; kk < 64; ++kk) {
        int kg = kc * 64 + kk;
        float a0 = a_sm[kg * A_PAD + rb + 0];
        float a1 = a_sm[kg * A_PAD + rb + 1];
        float a2 = a_sm[kg * A_PAD + rb + 2];
        float a3 = a_sm[kg * A_PAD + rb + 3];
        int cx = ((kk >> 3) & 7) << 2;
        const float4 b0 = *(const float4*)&b_sm[kk * 128 + (cA ^ cx)];
        const float4 b1 = *(const float4*)&b_sm[kk * 128 + (cB ^ cx)];
        float bj[8] = {b0.x, b0.y, b0.z, b0.w, b1.x, b1.y, b1.z, b1.w};
        float ai[4] = {a0, a1, a2, a3};
#pragma unroll
        for (int i = 0; i < 4; ++i)
#pragma unroll
            for (int j = 0; j < 8; ++j)
                acc[i][j] = fmaf(ai[i], bj[j], acc[i][j]);
    }
}

template <int MODE>
__global__ void __launch_bounds__(256, 2)
gemm_k(const float* __restrict__ A, const float* __restrict__ Bg, int ldb,
       const float* __restrict__ bias, float* __restrict__ C) {
    extern __shared__ float sm[];
    float* a_sm = sm;
    float* b_sm = sm + 256 * A_PAD;
    int tid = threadIdx.x;

    int mt = blockIdx.x >> 1, nt = blockIdx.x & 1;
    int row0 = mt * 64;
    fill_a(a_sm, A, row0, tid);
    __syncthreads();

    int trow = tid >> 4, tc = tid & 15;
    int rb = trow * 4;

    float acc[4][8];
#pragma unroll
    for (int i = 0; i < 4; ++i)
#pragma unroll
        for (int j = 0; j < 8; ++j) acc[i][j] = 0.f;

#pragma unroll 1
    for (int kc = 0; kc < 4; ++kc) {
        if (kc) __syncthreads();
        fill_b(b_sm, Bg, ldb, nt * 128, kc, tid);
        __syncthreads();
        compute_chunk(a_sm, b_sm, acc, kc, rb, tc);
    }

    int c0 = nt * 128 + tc * 4;
    int c1 = c0 + 64;
    if (MODE == M_GCN1 || MODE == M_GCN2) {
        float bv0[4], bv1[4];
#pragma unroll
        for (int j = 0; j < 4; ++j) { bv0[j] = bias[c0 + j]; bv1[j] = bias[c1 + j]; }
#pragma unroll
        for (int i = 0; i < 4; ++i) {
            size_t ro = (size_t)(row0 + rb + i) * 256;
            float o[8];
#pragma unroll
            for (int j = 0; j < 4; ++j) {
                o[j] = acc[i][j] + bv0[j];
                o[4 + j] = acc[i][4 + j] + bv1[j];
            }
            if (MODE == M_GCN1) {
#pragma unroll
                for (int j = 0; j < 8; ++j) o[j] = fmaxf(o[j], 0.f);
            }
            *(float4*)&C[ro + c0] = make_float4(o[0], o[1], o[2], o[3]);
            *(float4*)&C[ro + c1] = make_float4(o[4], o[5], o[6], o[7]);
        }
    } else { // M_SPAN: per-(w,b) row bias
#pragma unroll
        for (int i = 0; i < 4; ++i) {
            int row = row0 + rb + i;
            const float* rbp = bias + ((row >> 8) * 256);
            size_t ro = (size_t)row * 256;
            float o[8];
#pragma unroll
            for (int j = 0; j < 4; ++j) {
                o[j] = acc[i][j] + rbp[c0 + j];
                o[4 + j] = acc[i][4 + j] + rbp[c1 + j];
            }
            *(float4*)&C[ro + c0] = make_float4(o[0], o[1], o[2], o[3]);
            *(float4*)&C[ro + c1] = make_float4(o[4], o[5], o[6], o[7]);
        }
    }
}

// ------------------------- mma.sync sims + top-k filter --------------------
// grid (64 row-tiles, 2 esegs), 512 threads (16 warps).
// smem: A bf16 128x256 (64KB) @0, B stages 2x64KB @64KB.
// warp w: rows (w>>1)*16..+15, cols (w&1)*64..+63 of each 128x128 tile.

#define MK_SMEM (1024 + 196608)

__global__ void __launch_bounds__(512, 1)
mma_topk(const float* __restrict__ spanrepr) {
    extern __shared__ char rawsm[];
    char* smb = (char*)(((uintptr_t)rawsm + 1023) & ~(uintptr_t)1023);
    uint32_t sbase = smem_u32(smb);
    int tid = threadIdx.x;
    int w = tid >> 5, lane = tid & 31;

    int row0 = blockIdx.x * 128;
    int ebase = blockIdx.y * ESEG;
    int ntiles = blockIdx.y ? 195 : 196;

    // A tile: span_repr rows -> bf16 blocked SW128 layout
    for (int i = tid; i < 128 * 128; i += 512) {
        int r = i >> 7, c = (i & 127) * 2;
        float2 v = *(const float2*)&spanrepr[(size_t)(row0 + r) * 256 + c];
        __nv_bfloat162 bb = {__float2bfloat16(v.x), __float2bfloat16(v.y)};
        STS32(sbase + tileoff(r, c * 2), *(uint32_t*)&bb);
    }

    const int wr = (w >> 1) * 16;
    const int wc = (w & 1) * 64;

    // per-lane running top-8 for two rows (wr+(lane>>2), wr+8+(lane>>2))
    float tv1[8], tv2[8]; int ti1[8], ti2[8];
#pragma unroll
    for (int j = 0; j < 8; ++j) {
        tv1[j] = -FLT_MAX; ti1[j] = 0x7FFFFFFF;
        tv2[j] = -FLT_MAX; ti2[j] = 0x7FFFFFFF;
    }

    // ldmatrix lane address components (fixed per lane)
    const int a_r = wr + ((lane >> 3) & 1) * 8 + (lane & 7);
    const int a_cb = ((lane >> 4) & 1) * 16;
    const int b_rbase = wc + ((lane >> 4) & 1) * 8 + (lane & 7);
    const int b_cb = ((lane >> 3) & 1) * 16;

    // -------- B tile loader (cp.async) --------
    auto loadB = [&](int tile, int s) {
        int e0 = ebase + tile * 128;
        uint32_t bs = sbase + 65536 + s * 65536;
#pragma unroll
        for (int it = 0; it < 8; ++it) {
            int f = tid + it * 512;      // 0..4095 16B chunks
            int row = f >> 5, ch = f & 31;
            uint32_t dst = bs + tileoff(row, ch * 16);
            if (e0 + row < NE) {
                const void* src = &g_ETbf[(size_t)(e0 + row) * 256 + ch * 8];
                CP16(dst, src);
            } else {
                STS128(dst, 0u, 0u, 0u, 0u);
            }
        }
    };

    loadB(0, 0);
    CP_COMMIT();

#pragma unroll 1
    for (int i = 0; i < ntiles; ++i) {
        if (i + 1 < ntiles) loadB(i + 1, (i + 1) & 1);
        CP_COMMIT();
        CP_WAIT1();
        __syncthreads();

        uint32_t bufb = sbase + 65536 + (i & 1) * 65536;
        float acc[8][4];
#pragma unroll
        for (int nf = 0; nf < 8; ++nf)
#pragma unroll
            for (int j = 0; j < 4; ++j) acc[nf][j] = 0.f;

#pragma unroll 4
        for (int ks = 0; ks < 16; ++ks) {
            uint32_t a0, a1, a2, a3;
            LDMX4(a0, a1, a2, a3, sbase + tileoff(a_r, ks * 32 + a_cb));
#pragma unroll
            for (int p = 0; p < 4; ++p) {
                uint32_t b0, b1, b2, b3;
                LDMX4(b0, b1, b2, b3,
                      bufb + tileoff(b_rbase + p * 16, ks * 32 + b_cb));
                MMA16816(acc[2 * p], a0, a1, a2, a3, b0, b1);
                MMA16816(acc[2 * p + 1], a0, a1, a2, a3, b2, b3);
            }
        }

        // fold tile results into per-lane top-8 streams
        int e0 = ebase + i * 128 + wc + (lane & 3) * 2;
#pragma unroll
        for (int nf = 0; nf < 8; ++nf) {
            int e = e0 + nf * 8;
            if (e < NE) {
                insert8(tv1, ti1, acc[nf][0], e);
                insert8(tv2, ti2, acc[nf][2], e);
            }
            if (e + 1 < NE) {
                insert8(tv1, ti1, acc[nf][1], e + 1);
                insert8(tv2, ti2, acc[nf][3], e + 1);
            }
        }
        __syncthreads();
    }

    // -------- CTA merge: 8 streams/row -> top-16/row --------
    float* mv = (float*)(smb + 65536);            // [128][64]
    int* mi = (int*)(smb + 65536 + 32768);        // [128][64]
    int sid = (w & 1) * 4 + (lane & 3);
    int r1 = wr + (lane >> 2), r2 = r1 + 8;
#pragma unroll
    for (int j = 0; j < 8; ++j) {
        mv[r1 * 64 + sid * 8 + j] = tv1[j]; mi[r1 * 64 + sid * 8 + j] = ti1[j];
        mv[r2 * 64 + sid * 8 + j] = tv2[j]; mi[r2 * 64 + sid * 8 + j] = ti2[j];
    }
    __syncthreads();
    if (tid < 128) {
        float tv[16]; int ti[16];
#pragma unroll
        for (int j = 0; j < 16; ++j) { tv[j] = -FLT_MAX; ti[j] = 0x7FFFFFFF; }
        for (int q = 0; q < 64; ++q) {
            float v = mv[tid * 64 + q]; int e = mi[tid * 64 + q];
            if (better(v, e, tv[15], ti[15])) insert16_slow(tv, ti, v, e);
        }
        int* cp = &g_cand[((size_t)blockIdx.y * 8192 + row0 + tid) * 16];
#pragma unroll
        for (int j = 0; j < 16; ++j) cp[j] = ti[j];
    }
}

// ------------------------- exact fp32 refine -------------------------------
// one warp per row: 32 candidates, exact dot, top-8 with jax tie-break
__global__ void __launch_bounds__(256)
k_refine(const float* __restrict__ spanrepr, const float* __restrict__ ET) {
    int warp = threadIdx.x >> 5, lane = threadIdx.x & 31;
    int row = blockIdx.x * 8 + warp;

    __shared__ float sims[8][32];
    __shared__ int cidx[8][32];

    if (lane < 16) {
        cidx[warp][lane] = g_cand[((size_t)0 * 8192 + row) * 16 + lane];
        cidx[warp][16 + lane] = g_cand[((size_t)1 * 8192 + row) * 16 + lane];
    }
    float4 a0 = *(const float4*)&spanrepr[(size_t)row * 256 + lane * 8];
    float4 a1 = *(const float4*)&spanrepr[(size_t)row * 256 + lane * 8 + 4];
    __syncwarp();

#pragma unroll 1
    for (int c = 0; c < 32; ++c) {
        int idx = cidx[warp][c];
        const float4* ep = (const float4*)&ET[(size_t)idx * 256 + lane * 8];
        float4 e0 = ep[0], e1 = ep[1];
        float d = a0.x * e0.x + a0.y * e0.y + a0.z * e0.z + a0.w * e0.w
                + a1.x * e1.x + a1.y * e1.y + a1.z * e1.z + a1.w * e1.w;
#pragma unroll
        for (int o = 16; o; o >>= 1) d += __shfl_xor_sync(0xFFFFFFFFu, d, o);
        if (lane == 0) sims[warp][c] = d;
    }
    __syncwarp();
    if (lane == 0) {
        float tv[8]; int ti[8];
#pragma unroll
        for (int j = 0; j < 8; ++j) { tv[j] = -FLT_MAX; ti[j] = 0x7FFFFFFF; }
        for (int c = 0; c < 32; ++c) insert8(tv, ti, sims[warp][c], cidx[warp][c]);
#pragma unroll
        for (int j = 0; j < 8; ++j) g_topk[(size_t)row * 8 + j] = ti[j];
    }
}

// ------------------------- GCN mixing ---------------------------------------
__global__ void k_mix1(const float* __restrict__ ET) {
    int n = blockIdx.x, h = threadIdx.x;
    __shared__ int id[8];
    if (h < 8) id[h] = g_topk[n * 8 + h];
    __syncthreads();
    float x0 = ET[(size_t)id[0] * 256 + h];
    float s = 0.f;
    float* outb = g_mixed + (size_t)n * 8 * 256 + h;
#pragma unroll
    for (int j = 1; j < 8; ++j) {
        float xj = ET[(size_t)id[j] * 256 + h];
        s += xj;
        outb[j * 256] = 0.25f * x0 + 0.5f * xj;
    }
    outb[0] = 0.125f * x0 + 0.25f * s;
}

__global__ void k_mix2() {
    int n = blockIdx.x, h = threadIdx.x;
    const float* inb = g_hbuf + (size_t)n * 8 * 256 + h;
    float* outb = g_mixed + (size_t)n * 8 * 256 + h;
    float x0 = inb[0];
    float s = 0.f;
#pragma unroll
    for (int j = 1; j < 8; ++j) {
        float xj = inb[j * 256];
        s += xj;
        outb[j * 256] = 0.25f * x0 + 0.5f * xj;
    }
    outb[0] = 0.125f * x0 + 0.25f * s;
}

// ------------------------- host --------------------------------------------
extern "C" void kernel_launch(void* const* d_in, const int* in_sizes, int n_in,
                              void* d_out, int out_size) {
    const float* emb = (const float*)d_in[0];
    const float* ET = (const float*)d_in[1];
    const float* spanW = (const float*)d_in[2];
    const float* spanb = (const float*)d_in[3];
    const float* W1 = (const float*)d_in[4];
    const float* b1 = (const float*)d_in[5];
    const float* W2 = (const float*)d_in[6];
    const float* b2 = (const float*)d_in[7];

    float* out = (float*)d_out;
    float* out_cls = out;                       // 4*256
    float* out_spanrepr = out + 1024;           // 8192*256
    float* out_sub = out + 1024 + 8192 * 256;   // 65536*256

    float *spanmax, *rowbias, *mixed, *hbuf;
    cudaGetSymbolAddress((void**)&spanmax, g_spanmax);
    cudaGetSymbolAddress((void**)&rowbias, g_rowbias);
    cudaGetSymbolAddress((void**)&mixed, g_mixed);
    cudaGetSymbolAddress((void**)&hbuf, g_hbuf);

    cudaFuncSetAttribute(gemm_k<M_SPAN>, cudaFuncAttributeMaxDynamicSharedMemorySize, SMEM_BYTES);
    cudaFuncSetAttribute(gemm_k<M_GCN1>, cudaFuncAttributeMaxDynamicSharedMemorySize, SMEM_BYTES);
    cudaFuncSetAttribute(gemm_k<M_GCN2>, cudaFuncAttributeMaxDynamicSharedMemorySize, SMEM_BYTES);
    cudaFuncSetAttribute(mma_topk, cudaFuncAttributeMaxDynamicSharedMemorySize, MK_SMEM);

    // 1) entity table -> bf16
    k_etbf<<<NE * 256 / 1024, 256>>>(ET);
    // 2) cls + span max
    k_spanprep<<<1024, TPB>>>(emb, out_cls);
    // 3) per-(w,b) bias rows
    k_rowbias<<<32, TPB>>>(emb, spanW, spanb);
    // 4) span_repr = spanmax @ W[0:256] + rowbias
    gemm_k<M_SPAN><<<256, TPB, SMEM_BYTES>>>(spanmax, spanW, 256, rowbias, out_spanrepr);
    // 5) mma.sync bf16 sims + per-eseg top-16 candidate filter
    mma_topk<<<dim3(64, 2), 512, MK_SMEM>>>(out_spanrepr);
    // 6) exact fp32 refine -> sorted top-8
    k_refine<<<1024, 256>>>(out_spanrepr, ET);
    // 7) gather + star mix
    k_mix1<<<NROWS, TPB>>>(ET);
    // 8) hidden = relu(mixed @ W1 + b1)
    gemm_k<M_GCN1><<<2048, TPB, SMEM_BYTES>>>(mixed, W1, 256, b1, hbuf);
    // 9) star mix of hidden
    k_mix2<<<NROWS, TPB>>>();
    // 10) subgraph_out = mixed2 @ W2 + b2
    gemm_k<M_GCN2><<<2048, TPB, SMEM_BYTES>>>(mixed, W2, 256, b2, out_sub);

    (void)in_sizes; (void)n_in; (void)out_size;
}

// round 6
// speedup vs baseline: 3.0209x; 1.0015x over previous
#include <cuda_runtime.h>
#include <cuda_bf16.h>
#include <cstdint>
#include <cfloat>

// ---------------------------------------------------------------------------
// SpanModel: cls, span_repr = spanMLP(spanmax,cls,width), top8(entity sims),
// star-GCN (2 layers). sims via mma.sync bf16 filter (bulk-DMA B tiles)
// + exact fp32 refine.
// ---------------------------------------------------------------------------

#define TPB 256
#define A_PAD 65
#define SMEM_FLOATS (256 * A_PAD + 64 * 128)
#define SMEM_BYTES (SMEM_FLOATS * 4)

enum { M_SPAN = 0, M_GCN1 = 1, M_GCN2 = 2 };

static const int NE = 50000;
static const int NEP = 50176;        // padded to 392*128
static const int NROWS = 8192;       // Wmax*B*S
static const int NTILES_SEG = 196;   // tiles per entity segment (392/2)

// ------------------------- scratch (device globals) -----------------------
__device__ __align__(16) uint8_t g_ETraw[(size_t)NEP * 512]; // bf16, tile-blocked SW128
__device__ float g_spanmax[8L * 1024 * 256];   // [w][b][s][h]
__device__ float g_rowbias[32 * 256];          // per (w,b) bias row
__device__ int   g_cand[2L * 8192 * 16];       // candidate indices per eseg
__device__ int   g_topk[8192L * 8];            // final sorted top-8 indices
__device__ float g_mixed[65536L * 256];        // star-mixed features
__device__ float g_hbuf[65536L * 256];         // relu hidden

// ------------------------- PTX helpers -------------------------------------
__device__ __forceinline__ uint32_t smem_u32(const void* p) {
    uint32_t a;
    asm("{ .reg .u64 t; cvta.to.shared.u64 t, %1; cvt.u32.u64 %0, t; }"
        : "=r"(a) : "l"(p));
    return a;
}

#define STS32(addr, v) \
    asm volatile("st.shared.b32 [%0], %1;" :: "r"(addr), "r"(v) : "memory")

#define MBAR_INIT(addr, cnt) \
    asm volatile("mbarrier.init.shared.b64 [%0], %1;" :: "r"(addr), "r"(cnt) : "memory")
#define MBAR_ARRIVE(addr) \
    asm volatile("mbarrier.arrive.shared.b64 _, [%0];" :: "r"(addr) : "memory")
#define MBAR_EXPECT_TX(addr, bytes) \
    asm volatile("mbarrier.arrive.expect_tx.shared.b64 _, [%0], %1;" \
                 :: "r"(addr), "r"(bytes) : "memory")
#define BULK_LD(dst, src, bytes, mbar) \
    asm volatile("cp.async.bulk.shared::cta.global.mbarrier::complete_tx::bytes " \
                 "[%0], [%1], %2, [%3];" \
                 :: "r"(dst), "l"(src), "r"(bytes), "r"(mbar) : "memory")

__device__ __forceinline__ void waitp(uint32_t mbar, uint32_t phase) {
    asm volatile(
        "{\n\t.reg .pred P;\n\t"
        "WL%=:\n\t"
        "mbarrier.try_wait.parity.acquire.cta.shared::cta.b64 P, [%0], %1, 0x989680;\n\t"
        "@P bra WD%=;\n\t"
        "bra WL%=;\n\t"
        "WD%=:\n\t}"
        :: "r"(mbar), "r"(phase) : "memory");
}

#define LDMX4(r0, r1, r2, r3, addr) \
    asm volatile("ldmatrix.sync.aligned.m8n8.x4.shared.b16 {%0,%1,%2,%3}, [%4];" \
                 : "=r"(r0), "=r"(r1), "=r"(r2), "=r"(r3) : "r"(addr))

#define MMA16816(c, a0, a1, a2, a3, b0, b1) \
    asm volatile("mma.sync.aligned.m16n8k16.row.col.f32.bf16.bf16.f32 " \
                 "{%0,%1,%2,%3}, {%4,%5,%6,%7}, {%8,%9}, {%0,%1,%2,%3};" \
                 : "+f"((c)[0]), "+f"((c)[1]), "+f"((c)[2]), "+f"((c)[3]) \
                 : "r"(a0), "r"(a1), "r"(a2), "r"(a3), "r"(b0), "r"(b1))

// blocked SW128 layout for a 128-row x 512-byte bf16 tile (64 atoms x 1KB)
__device__ __forceinline__ uint32_t tileoff(int r, int cb) {
    int b = ((r >> 3) + (cb >> 7) * 16) * 1024 + (r & 7) * 128 + (cb & 127);
    return (uint32_t)(b ^ ((b >> 3) & 0x70));
}

// ------------------------- top-k helpers -----------------------------------
__device__ __forceinline__ bool better(float v1, int i1, float v2, int i2) {
    return (v1 > v2) || (v1 == v2 && i1 < i2);
}

__device__ __forceinline__ void insert8(float tv[8], int ti[8], float v, int e) {
    if (better(v, e, tv[7], ti[7])) {
        tv[7] = v; ti[7] = e;
#pragma unroll
        for (int j = 7; j > 0; --j) {
            if (better(tv[j], ti[j], tv[j - 1], ti[j - 1])) {
                float fv = tv[j]; tv[j] = tv[j - 1]; tv[j - 1] = fv;
                int ii = ti[j]; ti[j] = ti[j - 1]; ti[j - 1] = ii;
            }
        }
    }
}

__device__ __noinline__ void insert16_slow(float* tv, int* ti, float v, int e) {
    int q = 15;
    while (q > 0 && better(v, e, tv[q - 1], ti[q - 1])) {
        tv[q] = tv[q - 1]; ti[q] = ti[q - 1]; --q;
    }
    tv[q] = v; ti[q] = e;
}

// ------------------------- small kernels -----------------------------------

// entity table fp32 -> bf16 in tile-blocked SW128 global layout (padded rows=0)
__global__ void k_etbf(const float* __restrict__ ET) {
    int g = blockIdx.x * 256 + threadIdx.x;   // one 16B output chunk
    int r = g >> 5, ch = g & 31;
    uint4 o = make_uint4(0u, 0u, 0u, 0u);
    if (r < NE) {
        const float4* s = (const float4*)&ET[(size_t)r * 256 + ch * 8];
        float4 v0 = s[0], v1 = s[1];
        __nv_bfloat162 p0 = {__float2bfloat16(v0.x), __float2bfloat16(v0.y)};
        __nv_bfloat162 p1 = {__float2bfloat16(v0.z), __float2bfloat16(v0.w)};
        __nv_bfloat162 p2 = {__float2bfloat16(v1.x), __float2bfloat16(v1.y)};
        __nv_bfloat162 p3 = {__float2bfloat16(v1.z), __float2bfloat16(v1.w)};
        o = make_uint4(*(uint32_t*)&p0, *(uint32_t*)&p1, *(uint32_t*)&p2, *(uint32_t*)&p3);
    }
    size_t tile = (size_t)(r >> 7);
    *(uint4*)(g_ETraw + tile * 65536 + tileoff(r & 127, ch * 16)) = o;
}

// cls out + running span max over widths 1..8
__global__ void k_spanprep(const float* __restrict__ emb, float* __restrict__ out_cls) {
    int g = blockIdx.x * TPB + threadIdx.x;   // b*65536 + s*256 + h
    int h = g & 255, s = (g >> 8) & 255, b = g >> 16;
    float v0 = emb[g];
    float cur = v0;
    g_spanmax[g] = cur;
#pragma unroll
    for (int w = 1; w < 8; ++w) {
        if (s + w < 256) cur = fmaxf(cur, emb[((size_t)b * 256 + s + w) * 256 + h]);
        g_spanmax[(size_t)w * 262144 + g] = cur;
    }
    if (s == 0) out_cls[b * 256 + h] = v0;
}

// rowbias[w*4+b][h] = span_b[h] + (w+1)*W[512][h] + sum_j cls[b][j]*W[256+j][h]
__global__ void k_rowbias(const float* __restrict__ emb, const float* __restrict__ spanW,
                          const float* __restrict__ spanb) {
    int bw = blockIdx.x;
    int w = bw >> 2, b = bw & 3;
    int h = threadIdx.x;
    __shared__ float cls_s[256];
    cls_s[h] = emb[(size_t)b * 65536 + h];
    __syncthreads();
    float acc = spanb[h] + (float)(w + 1) * spanW[512 * 256 + h];
    for (int j = 0; j < 256; ++j)
        acc = fmaf(cls_s[j], spanW[(256 + j) * 256 + h], acc);
    g_rowbias[bw * 256 + h] = acc;
}

// ------------------------- FFMA GEMM (span/GCN) ----------------------------

__device__ __forceinline__ void fill_a(float* a_sm, const float* __restrict__ A,
                                       int row0, int tid) {
#pragma unroll
    for (int it = 0; it < 16; ++it) {
        int f = tid + 256 * it;
        int r = f >> 6;
        int q = f & 63;
        float4 v = *(const float4*)&A[((size_t)(row0 + r)) * 256 + 4 * q];
        a_sm[(4 * q + 0) * A_PAD + r] = v.x;
        a_sm[(4 * q + 1) * A_PAD + r] = v.y;
        a_sm[(4 * q + 2) * A_PAD + r] = v.z;
        a_sm[(4 * q + 3) * A_PAD + r] = v.w;
    }
}

__device__ __forceinline__ void fill_b(float* b_sm, const float* __restrict__ Bg,
                                       int ldb, int colBase, int kc, int tid) {
#pragma unroll
    for (int it = 0; it < 8; ++it) {
        int f = tid + 256 * it;
        int kk = f >> 5;
        int e4 = f & 31;
        int gc = colBase + 4 * e4;
        float4 v = *(const float4*)&Bg[((size_t)(kc * 64 + kk)) * ldb + gc];
        int cx = ((kk >> 3) & 7) << 2;
        *(float4*)&b_sm[kk * 128 + ((4 * e4) ^ cx)] = v;
    }
}

__device__ __forceinline__ void compute_chunk(const float* __restrict__ a_sm,
                                              const float* __restrict__ b_sm,
                                              float acc[4][8], int kc, int rb, int tc) {
    const int cA = tc * 4;
    const int cB = 64 + tc * 4;
#pragma unroll 8
    for (int kk = 0; kk < 64; ++kk) {
        int kg = kc * 64 + kk;
        float a0 = a_sm[kg * A_PAD + rb + 0];
        float a1 = a_sm[kg * A_PAD + rb + 1];
        float a2 = a_sm[kg * A_PAD + rb + 2];
        float a3 = a_sm[kg * A_PAD + rb + 3];
        int cx = ((kk >> 3) & 7) << 2;
        const float4 b0 = *(const float4*)&b_sm[kk * 128 + (cA ^ cx)];
        const float4 b1 = *(const float4*)&b_sm[kk * 128 + (cB ^ cx)];
        float bj[8] = {b0.x, b0.y, b0.z, b0.w, b1.x, b1.y, b1.z, b1.w};
        float ai[4] = {a0, a1, a2, a3};
#pragma unroll
        for (int i = 0; i < 4; ++i)
#pragma unroll
            for (int j = 0; j < 8; ++j)
                acc[i][j] = fmaf(ai[i], bj[j], acc[i][j]);
    }
}

template <int MODE>
__global__ void __launch_bounds__(256, 2)
gemm_k(const float* __restrict__ A, const float* __restrict__ Bg, int ldb,
       const float* __restrict__ bias, float* __restrict__ C) {
    extern __shared__ float sm[];
    float* a_sm = sm;
    float* b_sm = sm + 256 * A_PAD;
    int tid = threadIdx.x;

    int mt = blockIdx.x >> 1, nt = blockIdx.x & 1;
    int row0 = mt * 64;
    fill_a(a_sm, A, row0, tid);
    __syncthreads();

    int trow = tid >> 4, tc = tid & 15;
    int rb = trow * 4;

    float acc[4][8];
#pragma unroll
    for (int i = 0; i < 4; ++i)
#pragma unroll
        for (int j = 0; j < 8; ++j) acc[i][j] = 0.f;

#pragma unroll 1
    for (int kc = 0; kc < 4; ++kc) {
        if (kc) __syncthreads();
        fill_b(b_sm, Bg, ldb, nt * 128, kc, tid);
        __syncthreads();
        compute_chunk(a_sm, b_sm, acc, kc, rb, tc);
    }

    int c0 = nt * 128 + tc * 4;
    int c1 = c0 + 64;
    if (MODE == M_GCN1 || MODE == M_GCN2) {
        float bv0[4], bv1[4];
#pragma unroll
        for (int j = 0; j < 4; ++j) { bv0[j] = bias[c0 + j]; bv1[j] = bias[c1 + j]; }
#pragma unroll
        for (int i = 0; i < 4; ++i) {
            size_t ro = (size_t)(row0 + rb + i) * 256;
            float o[8];
#pragma unroll
            for (int j = 0; j < 4; ++j) {
                o[j] = acc[i][j] + bv0[j];
                o[4 + j] = acc[i][4 + j] + bv1[j];
            }
            if (MODE == M_GCN1) {
#pragma unroll
                for (int j = 0; j < 8; ++j) o[j] = fmaxf(o[j], 0.f);
            }
            *(float4*)&C[ro + c0] = make_float4(o[0], o[1], o[2], o[3]);
            *(float4*)&C[ro + c1] = make_float4(o[4], o[5], o[6], o[7]);
        }
    } else { // M_SPAN: per-(w,b) row bias
#pragma unroll
        for (int i = 0; i < 4; ++i) {
            int row = row0 + rb + i;
            const float* rbp = bias + ((row >> 8) * 256);
            size_t ro = (size_t)row * 256;
            float o[8];
#pragma unroll
            for (int j = 0; j < 4; ++j) {
                o[j] = acc[i][j] + rbp[c0 + j];
                o[4 + j] = acc[i][4 + j] + rbp[c1 + j];
            }
            *(float4*)&C[ro + c0] = make_float4(o[0], o[1], o[2], o[3]);
            *(float4*)&C[ro + c1] = make_float4(o[4], o[5], o[6], o[7]);
        }
    }
}

// ------------------------- mma.sync sims + top-k filter --------------------
// grid (64 row-tiles, 2 esegs), 512 threads (16 warps).
// smem: A bf16 128x256 (64KB) @0, B stages 2x64KB @64KB (bulk-DMA'd), bars @192KB.
// warp w: rows (w>>1)*16..+15, cols (w&1)*64..+63 of each 128x128 tile.

#define MK_SMEM (1024 + 196608 + 128)

__global__ void __launch_bounds__(512, 1)
mma_topk(const float* __restrict__ spanrepr) {
    extern __shared__ char rawsm[];
    char* smb = (char*)(((uintptr_t)rawsm + 1023) & ~(uintptr_t)1023);
    uint32_t sbase = smem_u32(smb);
    const uint32_t BARS = sbase + 196608;
    // full0@+0 full1@+8 empty0@+16 empty1@+24
    int tid = threadIdx.x;
    int w = tid >> 5, lane = tid & 31;

    int row0 = blockIdx.x * 128;
    int ebase = blockIdx.y * (NTILES_SEG * 128);
    int tbase = blockIdx.y * NTILES_SEG;

    if (tid == 0) {
        MBAR_INIT(BARS + 0, 1);  MBAR_INIT(BARS + 8, 1);    // full (tx-based)
        MBAR_INIT(BARS + 16, 16); MBAR_INIT(BARS + 24, 16); // empty (16 warps)
    }

    // A tile: span_repr rows -> bf16 blocked SW128 layout
    for (int i = tid; i < 128 * 128; i += 512) {
        int r = i >> 7, c = (i & 127) * 2;
        float2 v = *(const float2*)&spanrepr[(size_t)(row0 + r) * 256 + c];
        __nv_bfloat162 bb = {__float2bfloat16(v.x), __float2bfloat16(v.y)};
        STS32(sbase + tileoff(r, c * 2), *(uint32_t*)&bb);
    }
    __syncthreads();

    // prefetch tile 0
    if (tid == 0) {
        MBAR_EXPECT_TX(BARS + 0, 65536u);
        BULK_LD(sbase + 65536, (const void*)(g_ETraw + (size_t)tbase * 65536),
                65536u, BARS + 0);
    }

    const int wr = (w >> 1) * 16;
    const int wc = (w & 1) * 64;

    float tv1[8], tv2[8]; int ti1[8], ti2[8];
#pragma unroll
    for (int j = 0; j < 8; ++j) {
        tv1[j] = -FLT_MAX; ti1[j] = 0x7FFFFFFF;
        tv2[j] = -FLT_MAX; ti2[j] = 0x7FFFFFFF;
    }

    const int a_r = wr + ((lane >> 3) & 1) * 8 + (lane & 7);
    const int a_cb = ((lane >> 4) & 1) * 16;
    const int b_rbase = wc + ((lane >> 4) & 1) * 8 + (lane & 7);
    const int b_cb = ((lane >> 3) & 1) * 16;

#pragma unroll 1
    for (int i = 0; i < NTILES_SEG; ++i) {
        int s = i & 1, n = i >> 1;
        // prefetch tile i+1 into the other stage
        if (tid == 0 && i + 1 < NTILES_SEG) {
            int j = i + 1, s2 = j & 1;
            if (j >= 2) waitp(BARS + 16 + s2 * 8, ((j >> 1) + 1) & 1);
            MBAR_EXPECT_TX(BARS + 0 + s2 * 8, 65536u);
            BULK_LD(sbase + 65536 + s2 * 65536,
                    (const void*)(g_ETraw + (size_t)(tbase + j) * 65536),
                    65536u, BARS + 0 + s2 * 8);
        }
        waitp(BARS + 0 + s * 8, n & 1);

        uint32_t bufb = sbase + 65536 + s * 65536;
        float acc[8][4];
#pragma unroll
        for (int nf = 0; nf < 8; ++nf)
#pragma unroll
            for (int j = 0; j < 4; ++j) acc[nf][j] = 0.f;

#pragma unroll 4
        for (int ks = 0; ks < 16; ++ks) {
            uint32_t a0, a1, a2, a3;
            LDMX4(a0, a1, a2, a3, sbase + tileoff(a_r, ks * 32 + a_cb));
#pragma unroll
            for (int p = 0; p < 4; ++p) {
                uint32_t b0, b1, b2, b3;
                LDMX4(b0, b1, b2, b3,
                      bufb + tileoff(b_rbase + p * 16, ks * 32 + b_cb));
                MMA16816(acc[2 * p], a0, a1, a2, a3, b0, b1);
                MMA16816(acc[2 * p + 1], a0, a1, a2, a3, b2, b3);
            }
        }

        // fold tile results into per-lane top-8 streams (no NE guard: padded)
        int e0 = ebase + i * 128 + wc + (lane & 3) * 2;
#pragma unroll
        for (int nf = 0; nf < 8; ++nf) {
            int e = e0 + nf * 8;
            insert8(tv1, ti1, acc[nf][0], e);
            insert8(tv1, ti1, acc[nf][1], e + 1);
            insert8(tv2, ti2, acc[nf][2], e);
            insert8(tv2, ti2, acc[nf][3], e + 1);
        }
        // all LDSM results consumed (fold depends on acc) -> release stage
        if (lane == 0) MBAR_ARRIVE(BARS + 16 + s * 8);
    }

    // -------- CTA merge: 8 streams/row -> top-16/row --------
    __syncthreads();
    float* mv = (float*)(smb + 65536);            // [128][64]
    int* mi = (int*)(smb + 65536 + 32768);        // [128][64]
    int sid = (w & 1) * 4 + (lane & 3);
    int r1 = wr + (lane >> 2), r2 = r1 + 8;
#pragma unroll
    for (int j = 0; j < 8; ++j) {
        mv[r1 * 64 + sid * 8 + j] = tv1[j]; mi[r1 * 64 + sid * 8 + j] = ti1[j];
        mv[r2 * 64 + sid * 8 + j] = tv2[j]; mi[r2 * 64 + sid * 8 + j] = ti2[j];
    }
    __syncthreads();
    if (tid < 128) {
        float tv[16]; int ti[16];
#pragma unroll
        for (int j = 0; j < 16; ++j) { tv[j] = -FLT_MAX; ti[j] = 0x7FFFFFFF; }
        for (int q = 0; q < 64; ++q) {
            float v = mv[tid * 64 + q]; int e = mi[tid * 64 + q];
            if (better(v, e, tv[15], ti[15])) insert16_slow(tv, ti, v, e);
        }
        int* cp = &g_cand[((size_t)blockIdx.y * 8192 + row0 + tid) * 16];
#pragma unroll
        for (int j = 0; j < 16; ++j) cp[j] = ti[j];
    }
}

// ------------------------- exact fp32 refine -------------------------------
__global__ void __launch_bounds__(256)
k_refine(const float* __restrict__ spanrepr, const float* __restrict__ ET) {
    int warp = threadIdx.x >> 5, lane = threadIdx.x & 31;
    int row = blockIdx.x * 8 + warp;

    __shared__ float sims[8][32];
    __shared__ int cidx[8][32];

    if (lane < 16) {
        cidx[warp][lane] = g_cand[((size_t)0 * 8192 + row) * 16 + lane];
        cidx[warp][16 + lane] = g_cand[((size_t)1 * 8192 + row) * 16 + lane];
    }
    float4 a0 = *(const float4*)&spanrepr[(size_t)row * 256 + lane * 8];
    float4 a1 = *(const float4*)&spanrepr[(size_t)row * 256 + lane * 8 + 4];
    __syncwarp();

#pragma unroll 1
    for (int c = 0; c < 32; ++c) {
        int idx = cidx[warp][c];
        const float4* ep = (const float4*)&ET[(size_t)idx * 256 + lane * 8];
        float4 e0 = ep[0], e1 = ep[1];
        float d = a0.x * e0.x + a0.y * e0.y + a0.z * e0.z + a0.w * e0.w
                + a1.x * e1.x + a1.y * e1.y + a1.z * e1.z + a1.w * e1.w;
#pragma unroll
        for (int o = 16; o; o >>= 1) d += __shfl_xor_sync(0xFFFFFFFFu, d, o);
        if (lane == 0) sims[warp][c] = d;
    }
    __syncwarp();
    if (lane == 0) {
        float tv[8]; int ti[8];
#pragma unroll
        for (int j = 0; j < 8; ++j) { tv[j] = -FLT_MAX; ti[j] = 0x7FFFFFFF; }
        for (int c = 0; c < 32; ++c) insert8(tv, ti, sims[warp][c], cidx[warp][c]);
#pragma unroll
        for (int j = 0; j < 8; ++j) g_topk[(size_t)row * 8 + j] = ti[j];
    }
}

// ------------------------- GCN mixing ---------------------------------------
__global__ void k_mix1(const float* __restrict__ ET) {
    int n = blockIdx.x, h = threadIdx.x;
    __shared__ int id[8];
    if (h < 8) id[h] = g_topk[n * 8 + h];
    __syncthreads();
    float x0 = ET[(size_t)id[0] * 256 + h];
    float s = 0.f;
    float* outb = g_mixed + (size_t)n * 8 * 256 + h;
#pragma unroll
    for (int j = 1; j < 8; ++j) {
        float xj = ET[(size_t)id[j] * 256 + h];
        s += xj;
        outb[j * 256] = 0.25f * x0 + 0.5f * xj;
    }
    outb[0] = 0.125f * x0 + 0.25f * s;
}

__global__ void k_mix2() {
    int n = blockIdx.x, h = threadIdx.x;
    const float* inb = g_hbuf + (size_t)n * 8 * 256 + h;
    float* outb = g_mixed + (size_t)n * 8 * 256 + h;
    float x0 = inb[0];
    float s = 0.f;
#pragma unroll
    for (int j = 1; j < 8; ++j) {
        float xj = inb[j * 256];
        s += xj;
        outb[j * 256] = 0.25f * x0 + 0.5f * xj;
    }
    outb[0] = 0.125f * x0 + 0.25f * s;
}

// ------------------------- host --------------------------------------------
extern "C" void kernel_launch(void* const* d_in, const int* in_sizes, int n_in,
                              void* d_out, int out_size) {
    const float* emb = (const float*)d_in[0];
    const float* ET = (const float*)d_in[1];
    const float* spanW = (const float*)d_in[2];
    const float* spanb = (const float*)d_in[3];
    const float* W1 = (const float*)d_in[4];
    const float* b1 = (const float*)d_in[5];
    const float* W2 = (const float*)d_in[6];
    const float* b2 = (const float*)d_in[7];

    float* out = (float*)d_out;
    float* out_cls = out;                       // 4*256
    float* out_spanrepr = out + 1024;           // 8192*256
    float* out_sub = out + 1024 + 8192 * 256;   // 65536*256

    float *spanmax, *rowbias, *mixed, *hbuf;
    cudaGetSymbolAddress((void**)&spanmax, g_spanmax);
    cudaGetSymbolAddress((void**)&rowbias, g_rowbias);
    cudaGetSymbolAddress((void**)&mixed, g_mixed);
    cudaGetSymbolAddress((void**)&hbuf, g_hbuf);

    cudaFuncSetAttribute(gemm_k<M_SPAN>, cudaFuncAttributeMaxDynamicSharedMemorySize, SMEM_BYTES);
    cudaFuncSetAttribute(gemm_k<M_GCN1>, cudaFuncAttributeMaxDynamicSharedMemorySize, SMEM_BYTES);
    cudaFuncSetAttribute(gemm_k<M_GCN2>, cudaFuncAttributeMaxDynamicSharedMemorySize, SMEM_BYTES);
    cudaFuncSetAttribute(mma_topk, cudaFuncAttributeMaxDynamicSharedMemorySize, MK_SMEM);

    // 1) entity table -> bf16 tile-blocked SW128 (padded)
    k_etbf<<<(NEP * 32) / 256, 256>>>(ET);
    // 2) cls + span max
    k_spanprep<<<1024, TPB>>>(emb, out_cls);
    // 3) per-(w,b) bias rows
    k_rowbias<<<32, TPB>>>(emb, spanW, spanb);
    // 4) span_repr = spanmax @ W[0:256] + rowbias
    gemm_k<M_SPAN><<<256, TPB, SMEM_BYTES>>>(spanmax, spanW, 256, rowbias, out_spanrepr);
    // 5) mma.sync bf16 sims + per-eseg top-16 candidate filter
    mma_topk<<<dim3(64, 2), 512, MK_SMEM>>>(out_spanrepr);
    // 6) exact fp32 refine -> sorted top-8
    k_refine<<<1024, 256>>>(out_spanrepr, ET);
    // 7) gather + star mix
    k_mix1<<<NROWS, TPB>>>(ET);
    // 8) hidden = relu(mixed @ W1 + b1)
    gemm_k<M_GCN1><<<2048, TPB, SMEM_BYTES>>>(mixed, W1, 256, b1, hbuf);
    // 9) star mix of hidden
    k_mix2<<<NROWS, TPB>>>();
    // 10) subgraph_out = mixed2 @ W2 + b2
    gemm_k<M_GCN2><<<2048, TPB, SMEM_BYTES>>>(mixed, W2, 256, b2, out_sub);

    (void)in_sizes; (void)n_in; (void)out_size;
}